// round 16
// baseline (speedup 1.0000x reference)
#include <cuda_runtime.h>
#include <cstdint>
#include <cstddef>

#define TSTEPS 1024
#define BSZ 128
#define DSZ 256
#define HSZ 512
#define CSZ 1000
#define HPAD 516   // padded h row stride (floats)
#define HHALF 16   // batches per sub-scan half
#define HBYTES (HHALF * HPAD * 4)   // 33024 B per half bulk

// x-projections, layout [t][M=2048][b].  1 GB
__device__ float g_P[(size_t)TSTEPS * 4 * HSZ * BSZ];
// Double-buffered hidden state, layout [b][HPAD], tf32-rounded values.
__device__ float g_h2[2][BSZ * HPAD];
// Pre-converted tf32 operands
__device__ unsigned g_Wt32[2048 * 256];                   // [g*512+j][d]
__device__ unsigned g_xt32[(size_t)TSTEPS * BSZ * DSZ];   // [t][b][d]
// Barrier state
__device__ unsigned g_bar_count;
__device__ unsigned g_bar_gen;
__device__ unsigned g_flags[128 * 8];   // per CTA: [0]=half-A flag, [4]=half-B flag

__device__ __forceinline__ float fast_sigmoid(float x) {
    return __fdividef(1.0f, 1.0f + __expf(-x));
}
__device__ __forceinline__ float fast_tanh(float x) {
    return __fdividef(2.0f, 1.0f + __expf(-2.0f * x)) - 1.0f;
}
__device__ __forceinline__ unsigned cvt_tf32(float f) {
    unsigned u;
    asm("cvt.rna.tf32.f32 %0, %1;" : "=r"(u) : "f"(f));
    return u;
}

__device__ __forceinline__ void grid_barrier(unsigned nb) {
    __syncthreads();
    if (threadIdx.x == 0) {
        __threadfence();
        unsigned gen = *(volatile unsigned*)&g_bar_gen;
        unsigned arrived = atomicAdd(&g_bar_count, 1u);
        if (arrived == nb - 1u) {
            atomicExch(&g_bar_count, 0u);
            __threadfence();
            atomicAdd(&g_bar_gen, 1u);
        } else {
            while (*(volatile unsigned*)&g_bar_gen == gen) { __nanosleep(32); }
        }
        __threadfence();
    }
    __syncthreads();
}

__device__ __forceinline__ void publish_flag(int ct, int off, unsigned gen) {
    asm volatile("st.release.gpu.u32 [%0], %1;"
                 :: "l"(&g_flags[ct * 8 + off]), "r"(gen) : "memory");
}

__device__ __forceinline__ void cp16(void* dst_smem, const void* src) {
    unsigned d = (unsigned)__cvta_generic_to_shared(dst_smem);
    asm volatile("cp.async.cg.shared.global [%0], [%1], 16;\n" :: "r"(d), "l"(src));
}

// ---- mbarrier + TMA bulk helpers ----
__device__ __forceinline__ void mbar_init(unsigned mbar, unsigned count) {
    asm volatile("mbarrier.init.shared.b64 [%0], %1;" :: "r"(mbar), "r"(count) : "memory");
}
__device__ __forceinline__ void mbar_expect_tx(unsigned mbar, unsigned bytes) {
    asm volatile("mbarrier.arrive.expect_tx.shared.b64 _, [%0], %1;"
                 :: "r"(mbar), "r"(bytes) : "memory");
}
__device__ __forceinline__ void mbar_wait(unsigned mbar, unsigned parity) {
    asm volatile(
        "{\n\t"
        ".reg .pred P;\n\t"
        "LAB_%=:\n\t"
        "mbarrier.try_wait.parity.shared.b64 P, [%0], %1, 0x989680;\n\t"
        "@P bra DONE_%=;\n\t"
        "bra LAB_%=;\n\t"
        "DONE_%=:\n\t"
        "}"
        :: "r"(mbar), "r"(parity) : "memory");
}
__device__ __forceinline__ void bulk_g2s(unsigned dst_smem, const void* src,
                                         unsigned bytes, unsigned mbar) {
    asm volatile(
        "cp.async.bulk.shared::cluster.global.mbarrier::complete_tx::bytes "
        "[%0], [%1], %2, [%3];"
        :: "r"(dst_smem), "l"(src), "r"(bytes), "r"(mbar) : "memory");
}

#define MMA_TF32(c0,c1,c2,c3, a0,a1,a2,a3, b0,b1) \
    asm("mma.sync.aligned.m16n8k8.row.col.f32.tf32.tf32.f32 " \
        "{%0,%1,%2,%3}, {%4,%5,%6,%7}, {%8,%9}, {%0,%1,%2,%3};" \
        : "+f"(c0), "+f"(c1), "+f"(c2), "+f"(c3) \
        : "r"(a0), "r"(a1), "r"(a2), "r"(a3), "r"(b0), "r"(b1))

// ---------------------------------------------------------------------------
// Prep: W -> tf32 [M=g*512+j][d]
// ---------------------------------------------------------------------------
__global__ __launch_bounds__(256) void k_prep_w(
    const float* __restrict__ W0, const float* __restrict__ W1,
    const float* __restrict__ W2, const float* __restrict__ W3)
{
    int M = blockIdx.x;
    int g = M >> 9, j = M & 511;
    const float* W = (g == 0) ? W0 : (g == 1) ? W1 : (g == 2) ? W2 : W3;
    int d = threadIdx.x;
    g_Wt32[(size_t)M * 256 + d] = cvt_tf32(W[(size_t)d * HSZ + j]);
}

// Prep: x -> tf32 [t][b][d]
__global__ __launch_bounds__(64) void k_prep_x(const float* __restrict__ x)
{
    int t = blockIdx.x, b = blockIdx.y;
    int d4 = threadIdx.x * 4;
    float4 v = *(const float4*)&x[((size_t)b * TSTEPS + t) * DSZ + d4];
    uint4 o;
    o.x = cvt_tf32(v.x); o.y = cvt_tf32(v.y);
    o.z = cvt_tf32(v.z); o.w = cvt_tf32(v.w);
    *(uint4*)&g_xt32[((size_t)t * BSZ + b) * DSZ + d4] = o;
}

// ---------------------------------------------------------------------------
// Phase 1: tf32-mma GEMM, A resident, 16 timesteps per CTA (R14 form).
// ---------------------------------------------------------------------------
#define XP_TB 16
__global__ __launch_bounds__(256, 1) void k_xproj3()
{
    extern __shared__ unsigned smu[];
    unsigned* sA = smu;             // 128 x 260
    unsigned* sB = smu + 33280;     // 2 x 8704

    const int M0 = blockIdx.x * 128;
    const int t0 = blockIdx.y * XP_TB;
    const int tid = threadIdx.x;
    const int w = tid >> 5, lane = tid & 31;
    const int gp = lane >> 2, tg = lane & 3;

    const unsigned* Asrc = g_Wt32 + (size_t)M0 * 256;

#pragma unroll
    for (int i = 0; i < 32; ++i) {
        int linear = tid + i * 256;
        int row = linear >> 6, slot = (linear & 63) * 4;
        cp16(&sA[row * 260 + slot], &Asrc[row * 256 + slot]);
    }
    asm volatile("cp.async.commit_group;");

    {
        const unsigned* Bsrc = g_xt32 + (size_t)t0 * BSZ * DSZ;
#pragma unroll
        for (int i = 0; i < 8; ++i) {
            int linear = tid + i * 256;
            int row = linear >> 4, slot = (linear & 15) * 4;
            cp16(&sB[row * 68 + slot], &Bsrc[row * 256 + slot]);
        }
    }
    asm volatile("cp.async.commit_group;");

    float acc[16][4];
#pragma unroll
    for (int f = 0; f < 16; ++f)
#pragma unroll
        for (int q = 0; q < 4; ++q) acc[f][q] = 0.0f;

    const int rA = (w * 16 + gp) * 260, rB = (w * 16 + gp + 8) * 260;

    for (int q = 0; q < XP_TB * 4; ++q) {
        if (q < XP_TB * 4 - 1) {
            int qn = q + 1;
            int tl = qn >> 2, c = qn & 3;
            const unsigned* Bsrc = g_xt32 + (size_t)(t0 + tl) * BSZ * DSZ + c * 64;
            unsigned* dB = sB + (qn & 1) * 8704;
#pragma unroll
            for (int i = 0; i < 8; ++i) {
                int linear = tid + i * 256;
                int row = linear >> 4, slot = (linear & 15) * 4;
                cp16(&dB[row * 68 + slot], &Bsrc[row * 256 + slot]);
            }
            asm volatile("cp.async.commit_group;");
            asm volatile("cp.async.wait_group 1;");
        } else {
            asm volatile("cp.async.wait_group 0;");
        }
        __syncthreads();
        const unsigned* B = sB + (q & 1) * 8704;
        const int kofs = (q & 3) * 64;
#pragma unroll
        for (int ksl = 0; ksl < 8; ++ksl) {
            int k0 = ksl * 8 + tg;
            unsigned a0 = sA[rA + kofs + k0];
            unsigned a1 = sA[rB + kofs + k0];
            unsigned a2 = sA[rA + kofs + k0 + 4];
            unsigned a3 = sA[rB + kofs + k0 + 4];
#pragma unroll
            for (int f = 0; f < 16; ++f) {
                unsigned b0 = B[(f * 8 + gp) * 68 + k0];
                unsigned b1 = B[(f * 8 + gp) * 68 + k0 + 4];
                MMA_TF32(acc[f][0], acc[f][1], acc[f][2], acc[f][3],
                         a0, a1, a2, a3, b0, b1);
            }
        }
        __syncthreads();

        if ((q & 3) == 3) {
            int t = t0 + (q >> 2);
            const size_t rbase = ((size_t)t * 2048 + M0 + w * 16 + gp) * 128;
#pragma unroll
            for (int f = 0; f < 16; ++f) {
                *(float2*)&g_P[rbase + f * 8 + tg * 2] =
                    make_float2(acc[f][0], acc[f][1]);
                *(float2*)&g_P[rbase + (size_t)8 * 128 + f * 8 + tg * 2] =
                    make_float2(acc[f][2], acc[f][3]);
                acc[f][0] = acc[f][1] = acc[f][2] = acc[f][3] = 0.0f;
            }
        }
    }
}

// ---------------------------------------------------------------------------
// Phase 2: persistent tf32-mma scan, TWO interleaved independent sub-scans.
// 128 CTAs = 32 row-groups (mg) x 4 batch-groups (ng); each ng group's 32
// batches split into halves A (b 0-15) and B (b 16-31) that form independent
// 16-batch scans. While half X's flags/TMA are in flight, compute half Y.
// Warp tiling per half: 8 warps = 4 m16-tiles x 2 n8-tiles; K=512 resident A.
// SMEM: A 131072 | hA 33024 | hB 33024 | E 64x18x4=4608  -> 201728 B
// ---------------------------------------------------------------------------
__global__ __launch_bounds__(256, 1) void k_rnn6(
    const float* __restrict__ Wgh, const float* __restrict__ Wih,
    const float* __restrict__ Wfh, const float* __restrict__ Woh,
    const float* __restrict__ bgp, const float* __restrict__ bip,
    const float* __restrict__ bfp, const float* __restrict__ bop)
{
    extern __shared__ float sm[];
    unsigned* sAu = (unsigned*)sm;                  // 32768 u
    float* sh_hA = sm + 32768;                      // 16 x 516
    float* sh_hB = sm + 32768 + 16 * HPAD;          // 16 x 516
    float* sh_E  = sm + 32768 + 32 * HPAD;          // 64 x 18
    __shared__ __align__(8) unsigned long long mbar_store[2];
    const unsigned mbarA = (unsigned)__cvta_generic_to_shared(&mbar_store[0]);
    const unsigned mbarB = (unsigned)__cvta_generic_to_shared(&mbar_store[1]);

    const int ct = blockIdx.x;
    const int mg = ct >> 2, ng = ct & 3;
    const int j0 = mg * 16;
    const int nbase = ng * 32;
    const int tid = threadIdx.x;
    const int w = tid >> 5, lane = tid & 31;
    const int mt = w & 3, nh = w >> 2;      // m16 tile, n8 tile (0..1)
    const int gp = lane >> 2, tg = lane & 3;

    // build pre-swizzled tf32 A fragments (once) — same layout as R11/R14
    {
        const float* Wt[4] = {Wgh, Wih, Wfh, Woh};
        for (int idx = tid; idx < 32768; idx += 256) {
            int mtb = idx >> 13;
            int rem = idx & 8191;
            int ks = rem >> 7;
            int ln = (rem >> 2) & 31;
            int q = rem & 3;
            int gpp = ln >> 2, tgg = ln & 3;
            int rowl = mtb * 16 + gpp + ((q & 1) << 3);
            int k = ks * 8 + tgg + ((q >> 1) << 2);
            int gate = rowl & 3;
            int j = j0 + (rowl >> 2);
            sAu[idx] = cvt_tf32(Wt[gate][(size_t)k * HSZ + j]);
        }
    }

    const int mA = mt * 16 + gp, mB = mA + 8;
    const int gateA = mA & 3, gateB = mB & 3;
    const int jA = j0 + (mA >> 2), jB = j0 + (mB >> 2);
    const size_t rowA = (size_t)gateA * HSZ + jA;
    const size_t rowB = (size_t)gateB * HSZ + jB;
    // P column for half hf: nbase + hf*16 + nh*8 + tg*2
    const int cbA = nbase + nh * 8 + tg * 2;
    const int cbB = cbA + 16;

    const float* Bt0[4] = {bgp, bip, bfp, bop};
    const float biasA = Bt0[gateA][jA];
    const float biasB = Bt0[gateB][jB];

    // epilogue mapping: thread -> (jj 0..15, bl 0..15) of the current half
    const int e_jj = tid >> 4;
    const int e_bl = tid & 15;
    const int e_jglob = j0 + e_jj;

    // init: zero h[0] rows for this CTA (incl. padding), flags, mbarriers
    for (int i = tid; i < HPAD; i += 256) g_h2[0][(size_t)ct * HPAD + i] = 0.0f;
    if (tid == 0) {
        *(volatile unsigned*)&g_flags[ct * 8] = 0u;
        *(volatile unsigned*)&g_flags[ct * 8 + 4] = 0u;
        mbar_init(mbarA, 1u);
        mbar_init(mbarB, 1u);
    }
    grid_barrier(gridDim.x);

    float cstA = 0.0f, cstB = 0.0f;   // cell state, one per half

    // P prefetch (t=0), both halves
    float2 pA0, pA1, pB0, pB1;
    {
        const float* P0 = g_P;
        pA0 = *(const float2*)&P0[rowA * 128 + cbA];
        pA1 = *(const float2*)&P0[rowB * 128 + cbA];
        pB0 = *(const float2*)&P0[rowA * 128 + cbB];
        pB1 = *(const float2*)&P0[rowB * 128 + cbB];
    }

    const unsigned* Abase = sAu + (mt * 64) * 128 + lane * 4;
    const int nOff = (nh * 8 + gp) * HPAD;
    const unsigned shA_u32 = (unsigned)__cvta_generic_to_shared(sh_hA);
    const unsigned shB_u32 = (unsigned)__cvta_generic_to_shared(sh_hB);

    // prologue: issue bulk A(0)  (h zeroed; no flags needed)
    if (tid == 0) {
        mbar_expect_tx(mbarA, HBYTES);
        bulk_g2s(shA_u32, g_h2[0] + (size_t)nbase * HPAD, HBYTES, mbarA);
    }

    for (int t = 0; t < TSTEPS; ++t) {
        const int pb = t & 1;
        const float* hb = g_h2[pb];
        float* hn = g_h2[pb ^ 1];

        // warp 0: poll half-B writers for step t, issue bulk B(t)
        if (w == 0) {
            const unsigned* f = &g_flags[(lane * 4 + ng) * 8 + 4];
            unsigned v;
            while (true) {
                asm volatile("ld.acquire.gpu.u32 %0, [%1];" : "=r"(v) : "l"(f) : "memory");
                if (v >= (unsigned)t) break;
                __nanosleep(20);
            }
            __syncwarp();
            if (lane == 0) {
                mbar_expect_tx(mbarB, HBYTES);
                bulk_g2s(shB_u32, hb + (size_t)(nbase + 16) * HPAD, HBYTES, mbarB);
            }
        }

        // ---- half A ----
        float ce0 = pA0.x + biasA, ce1 = pA0.y + biasA;
        float ce2 = pA1.x + biasB, ce3 = pA1.y + biasB;
        float co0 = 0, co1 = 0, co2 = 0, co3 = 0;
        if (t + 1 < TSTEPS) {
            const float* Pn = g_P + (size_t)(t + 1) * 2048 * 128;
            pA0 = *(const float2*)&Pn[rowA * 128 + cbA];
            pA1 = *(const float2*)&Pn[rowB * 128 + cbA];
        }

        mbar_wait(mbarA, (unsigned)pb);
        {
            const unsigned* hu = (const unsigned*)sh_hA;
#pragma unroll 8
            for (int k2 = 0; k2 < 32; ++k2) {
                uint4 a0 = *(const uint4*)&Abase[(k2 * 2) * 128];
                uint4 a1 = *(const uint4*)&Abase[(k2 * 2 + 1) * 128];
                int kb = k2 * 16 + tg;
                unsigned b00 = hu[nOff + kb],     b01 = hu[nOff + kb + 4];
                MMA_TF32(ce0, ce1, ce2, ce3, a0.x, a0.y, a0.z, a0.w, b00, b01);
                unsigned b10 = hu[nOff + kb + 8], b11 = hu[nOff + kb + 12];
                MMA_TF32(co0, co1, co2, co3, a1.x, a1.y, a1.z, a1.w, b10, b11);
            }
        }
        {
            int col0 = nh * 8 + tg * 2;
            *(float2*)&sh_E[mA * 18 + col0] = make_float2(ce0 + co0, ce1 + co1);
            *(float2*)&sh_E[mB * 18 + col0] = make_float2(ce2 + co2, ce3 + co3);
        }
        __syncthreads();
        {
            float pg = sh_E[(e_jj * 4 + 0) * 18 + e_bl];
            float pi = sh_E[(e_jj * 4 + 1) * 18 + e_bl];
            float pfv= sh_E[(e_jj * 4 + 2) * 18 + e_bl];
            float po = sh_E[(e_jj * 4 + 3) * 18 + e_bl];
            float gv = fast_tanh(pg);
            float iv = fast_sigmoid(pi);
            float fv = fast_sigmoid(pfv);
            float ov = fast_sigmoid(po);
            cstA = gv * iv + cstA * fv;
            ((unsigned*)hn)[(size_t)(nbase + e_bl) * HPAD + e_jglob] =
                cvt_tf32(fast_tanh(cstA) * ov);
        }
        __syncthreads();
        if (tid == 0) publish_flag(ct, 0, (unsigned)(t + 1));

        // warp 0: poll half-A writers for step t+1, issue bulk A(t+1)
        if (t + 1 < TSTEPS && w == 0) {
            const unsigned* f = &g_flags[(lane * 4 + ng) * 8];
            unsigned v;
            while (true) {
                asm volatile("ld.acquire.gpu.u32 %0, [%1];" : "=r"(v) : "l"(f) : "memory");
                if (v >= (unsigned)(t + 1)) break;
                __nanosleep(20);
            }
            __syncwarp();
            if (lane == 0) {
                mbar_expect_tx(mbarA, HBYTES);
                bulk_g2s(shA_u32, hn + (size_t)nbase * HPAD, HBYTES, mbarA);
            }
        }

        // ---- half B ----
        float de0 = pB0.x + biasA, de1 = pB0.y + biasA;
        float de2 = pB1.x + biasB, de3 = pB1.y + biasB;
        float do0 = 0, do1 = 0, do2 = 0, do3 = 0;
        if (t + 1 < TSTEPS) {
            const float* Pn = g_P + (size_t)(t + 1) * 2048 * 128;
            pB0 = *(const float2*)&Pn[rowA * 128 + cbB];
            pB1 = *(const float2*)&Pn[rowB * 128 + cbB];
        }

        mbar_wait(mbarB, (unsigned)pb);
        {
            const unsigned* hu = (const unsigned*)sh_hB;
#pragma unroll 8
            for (int k2 = 0; k2 < 32; ++k2) {
                uint4 a0 = *(const uint4*)&Abase[(k2 * 2) * 128];
                uint4 a1 = *(const uint4*)&Abase[(k2 * 2 + 1) * 128];
                int kb = k2 * 16 + tg;
                unsigned b00 = hu[nOff + kb],     b01 = hu[nOff + kb + 4];
                MMA_TF32(de0, de1, de2, de3, a0.x, a0.y, a0.z, a0.w, b00, b01);
                unsigned b10 = hu[nOff + kb + 8], b11 = hu[nOff + kb + 12];
                MMA_TF32(do0, do1, do2, do3, a1.x, a1.y, a1.z, a1.w, b10, b11);
            }
        }
        {
            int col0 = nh * 8 + tg * 2;
            *(float2*)&sh_E[mA * 18 + col0] = make_float2(de0 + do0, de1 + do1);
            *(float2*)&sh_E[mB * 18 + col0] = make_float2(de2 + do2, de3 + do3);
        }
        __syncthreads();
        {
            float pg = sh_E[(e_jj * 4 + 0) * 18 + e_bl];
            float pi = sh_E[(e_jj * 4 + 1) * 18 + e_bl];
            float pfv= sh_E[(e_jj * 4 + 2) * 18 + e_bl];
            float po = sh_E[(e_jj * 4 + 3) * 18 + e_bl];
            float gv = fast_tanh(pg);
            float iv = fast_sigmoid(pi);
            float fv = fast_sigmoid(pfv);
            float ov = fast_sigmoid(po);
            cstB = gv * iv + cstB * fv;
            ((unsigned*)hn)[(size_t)(nbase + 16 + e_bl) * HPAD + e_jglob] =
                cvt_tf32(fast_tanh(cstB) * ov);
        }
        __syncthreads();
        if (tid == 0) publish_flag(ct, 4, (unsigned)(t + 1));
    }
}

// ---------------------------------------------------------------------------
// Phase 3: out[b][c] = h_final[b] . Wph[:,c] + bp[c].
// ---------------------------------------------------------------------------
__global__ __launch_bounds__(256) void k_out(
    const float* __restrict__ Wp, const float* __restrict__ bp,
    float* __restrict__ out)
{
    __shared__ float sh[HSZ];
    int b = blockIdx.x;
    const float* h = g_h2[0] + (size_t)b * HPAD;   // t=1023 writes buffer (1024&1)=0
    for (int i = threadIdx.x; i < HSZ; i += 256) sh[i] = h[i];
    __syncthreads();
    for (int c = threadIdx.x; c < CSZ; c += 256) {
        float acc = 0.0f;
#pragma unroll 8
        for (int k = 0; k < HSZ; ++k)
            acc += sh[k] * Wp[(size_t)k * CSZ + c];
        out[b * CSZ + c] = acc + bp[c];
    }
}

// ---------------------------------------------------------------------------

extern "C" void kernel_launch(void* const* d_in, const int* in_sizes, int n_in,
                              void* d_out, int out_size) {
    const float* x   = (const float*)d_in[0];
    const float* Wgx = (const float*)d_in[1];
    const float* Wgh = (const float*)d_in[2];
    const float* bg  = (const float*)d_in[3];
    const float* Wix = (const float*)d_in[4];
    const float* Wih = (const float*)d_in[5];
    const float* bi  = (const float*)d_in[6];
    const float* Wfx = (const float*)d_in[7];
    const float* Wfh = (const float*)d_in[8];
    const float* bf  = (const float*)d_in[9];
    const float* Wox = (const float*)d_in[10];
    const float* Woh = (const float*)d_in[11];
    const float* bo  = (const float*)d_in[12];
    const float* Wph = (const float*)d_in[13];
    const float* bp  = (const float*)d_in[14];
    float* out = (float*)d_out;

    (void)in_sizes; (void)n_in; (void)out_size;

    const int smem_xp  = 202752;                               // A 133120 + B 69632
    const int smem_rnn = (32768 + 32 * HPAD + 64 * 18) * 4;    // 201728 B
    cudaFuncSetAttribute(k_xproj3, cudaFuncAttributeMaxDynamicSharedMemorySize, smem_xp);
    cudaFuncSetAttribute(k_rnn6,   cudaFuncAttributeMaxDynamicSharedMemorySize, smem_rnn);

    k_prep_w<<<2048, 256>>>(Wgx, Wix, Wfx, Wox);
    k_prep_x<<<dim3(TSTEPS, BSZ), 64>>>(x);
    k_xproj3<<<dim3(16, TSTEPS / XP_TB), 256, smem_xp>>>();
    k_rnn6<<<128, 256, smem_rnn>>>(Wgh, Wih, Wfh, Woh, bg, bi, bf, bo);
    k_out<<<BSZ, 256>>>(Wph, bp, out);
}

// round 17
// speedup vs baseline: 1.1121x; 1.1121x over previous
#include <cuda_runtime.h>
#include <cstdint>
#include <cstddef>

#define TSTEPS 1024
#define BSZ 128
#define DSZ 256
#define HSZ 512
#define CSZ 1000
#define HPAD 516   // padded h row stride (floats): conflict-free smem cols, 2064B rows

// x-projections, layout [t][M=2048][b].  1 GB
__device__ float g_P[(size_t)TSTEPS * 4 * HSZ * BSZ];
// Double-buffered hidden state, layout [b][HPAD], tf32-rounded values.
__device__ float g_h2[2][BSZ * HPAD];
// Pre-converted tf32 operands
__device__ unsigned g_Wt32[2048 * 256];                   // [g*512+j][d]
__device__ unsigned g_xt32[(size_t)TSTEPS * BSZ * DSZ];   // [t][b][d]
// Barrier state
__device__ unsigned g_bar_count;
__device__ unsigned g_bar_gen;
__device__ unsigned g_flags[128 * 8];

// ---------------------------------------------------------------------------
// MUFU-free activations: exp2 via magic-round + deg-6 poly + exponent splice;
// reciprocal via bit-trick seed + 2 Newton iters. All FMA/ALU pipe.
// ---------------------------------------------------------------------------
__device__ __forceinline__ float fexp2p(float x) {
    // round-to-nearest-int via magic number (|x| <= ~64 here)
    float y = x + 12582912.0f;                       // 1.5 * 2^23
    int ei = __float_as_int(y) - 0x4B400000;         // integer part
    float f = x - (y - 12582912.0f);                 // frac in [-0.5, 0.5]
    float p = 1.5403530e-4f;
    p = fmaf(p, f, 1.3333558e-3f);
    p = fmaf(p, f, 9.6181291e-3f);
    p = fmaf(p, f, 5.5504109e-2f);
    p = fmaf(p, f, 2.4022651e-1f);
    p = fmaf(p, f, 6.9314718e-1f);
    p = fmaf(p, f, 1.0f);
    return __int_as_float(__float_as_int(p) + (ei << 23));
}
__device__ __forceinline__ float fast_sigmoid(float x) {
    x = fminf(fmaxf(x, -30.0f), 30.0f);
    float u = fexp2p(-1.44269504f * x);              // e^-x
    float d = 1.0f + u;
    float r = __int_as_float(0x7EF311C3 - __float_as_int(d));  // ~1/d seed
    r = r * (2.0f - d * r);
    r = r * (2.0f - d * r);
    return r;
}
__device__ __forceinline__ float fast_tanh(float x) {
    return fmaf(2.0f, fast_sigmoid(2.0f * x), -1.0f);
}

__device__ __forceinline__ unsigned cvt_tf32(float f) {
    unsigned u;
    asm("cvt.rna.tf32.f32 %0, %1;" : "=r"(u) : "f"(f));
    return u;
}

__device__ __forceinline__ void grid_barrier(unsigned nb) {
    __syncthreads();
    if (threadIdx.x == 0) {
        __threadfence();
        unsigned gen = *(volatile unsigned*)&g_bar_gen;
        unsigned arrived = atomicAdd(&g_bar_count, 1u);
        if (arrived == nb - 1u) {
            atomicExch(&g_bar_count, 0u);
            __threadfence();
            atomicAdd(&g_bar_gen, 1u);
        } else {
            while (*(volatile unsigned*)&g_bar_gen == gen) { __nanosleep(32); }
        }
        __threadfence();
    }
    __syncthreads();
}

__device__ __forceinline__ void publish_flag(int ct, unsigned gen) {
    asm volatile("st.release.gpu.u32 [%0], %1;"
                 :: "l"(&g_flags[ct * 8]), "r"(gen) : "memory");
}

__device__ __forceinline__ void cp16(void* dst_smem, const void* src) {
    unsigned d = (unsigned)__cvta_generic_to_shared(dst_smem);
    asm volatile("cp.async.cg.shared.global [%0], [%1], 16;\n" :: "r"(d), "l"(src));
}

// ---- mbarrier + TMA bulk helpers ----
__device__ __forceinline__ void mbar_init(unsigned mbar, unsigned count) {
    asm volatile("mbarrier.init.shared.b64 [%0], %1;" :: "r"(mbar), "r"(count) : "memory");
}
__device__ __forceinline__ void mbar_expect_tx(unsigned mbar, unsigned bytes) {
    asm volatile("mbarrier.arrive.expect_tx.shared.b64 _, [%0], %1;"
                 :: "r"(mbar), "r"(bytes) : "memory");
}
__device__ __forceinline__ void mbar_wait(unsigned mbar, unsigned parity) {
    asm volatile(
        "{\n\t"
        ".reg .pred P;\n\t"
        "LAB_%=:\n\t"
        "mbarrier.try_wait.parity.shared.b64 P, [%0], %1, 0x989680;\n\t"
        "@P bra DONE_%=;\n\t"
        "bra LAB_%=;\n\t"
        "DONE_%=:\n\t"
        "}"
        :: "r"(mbar), "r"(parity) : "memory");
}
__device__ __forceinline__ void bulk_g2s(unsigned dst_smem, const void* src,
                                         unsigned bytes, unsigned mbar) {
    asm volatile(
        "cp.async.bulk.shared::cluster.global.mbarrier::complete_tx::bytes "
        "[%0], [%1], %2, [%3];"
        :: "r"(dst_smem), "l"(src), "r"(bytes), "r"(mbar) : "memory");
}

#define MMA_TF32(c0,c1,c2,c3, a0,a1,a2,a3, b0,b1) \
    asm("mma.sync.aligned.m16n8k8.row.col.f32.tf32.tf32.f32 " \
        "{%0,%1,%2,%3}, {%4,%5,%6,%7}, {%8,%9}, {%0,%1,%2,%3};" \
        : "+f"(c0), "+f"(c1), "+f"(c2), "+f"(c3) \
        : "r"(a0), "r"(a1), "r"(a2), "r"(a3), "r"(b0), "r"(b1))

// ---------------------------------------------------------------------------
// Prep: W -> tf32 [M=g*512+j][d]
// ---------------------------------------------------------------------------
__global__ __launch_bounds__(256) void k_prep_w(
    const float* __restrict__ W0, const float* __restrict__ W1,
    const float* __restrict__ W2, const float* __restrict__ W3)
{
    int M = blockIdx.x;
    int g = M >> 9, j = M & 511;
    const float* W = (g == 0) ? W0 : (g == 1) ? W1 : (g == 2) ? W2 : W3;
    int d = threadIdx.x;
    g_Wt32[(size_t)M * 256 + d] = cvt_tf32(W[(size_t)d * HSZ + j]);
}

// Prep: x -> tf32 [t][b][d]
__global__ __launch_bounds__(64) void k_prep_x(const float* __restrict__ x)
{
    int t = blockIdx.x, b = blockIdx.y;
    int d4 = threadIdx.x * 4;
    float4 v = *(const float4*)&x[((size_t)b * TSTEPS + t) * DSZ + d4];
    uint4 o;
    o.x = cvt_tf32(v.x); o.y = cvt_tf32(v.y);
    o.z = cvt_tf32(v.z); o.w = cvt_tf32(v.w);
    *(uint4*)&g_xt32[((size_t)t * BSZ + b) * DSZ + d4] = o;
}

// ---------------------------------------------------------------------------
// Phase 1: tf32-mma GEMM, A (weights) resident in smem, 16 timesteps per CTA.
// grid (16 m-tiles, 64 t-groups), 256 threads.
// ---------------------------------------------------------------------------
#define XP_TB 16
__global__ __launch_bounds__(256, 1) void k_xproj3()
{
    extern __shared__ unsigned smu[];
    unsigned* sA = smu;             // 128 x 260
    unsigned* sB = smu + 33280;     // 2 x 8704

    const int M0 = blockIdx.x * 128;
    const int t0 = blockIdx.y * XP_TB;
    const int tid = threadIdx.x;
    const int w = tid >> 5, lane = tid & 31;
    const int gp = lane >> 2, tg = lane & 3;

    const unsigned* Asrc = g_Wt32 + (size_t)M0 * 256;

#pragma unroll
    for (int i = 0; i < 32; ++i) {
        int linear = tid + i * 256;
        int row = linear >> 6, slot = (linear & 63) * 4;
        cp16(&sA[row * 260 + slot], &Asrc[row * 256 + slot]);
    }
    asm volatile("cp.async.commit_group;");

    {
        const unsigned* Bsrc = g_xt32 + (size_t)t0 * BSZ * DSZ;
#pragma unroll
        for (int i = 0; i < 8; ++i) {
            int linear = tid + i * 256;
            int row = linear >> 4, slot = (linear & 15) * 4;
            cp16(&sB[row * 68 + slot], &Bsrc[row * 256 + slot]);
        }
    }
    asm volatile("cp.async.commit_group;");

    float acc[16][4];
#pragma unroll
    for (int f = 0; f < 16; ++f)
#pragma unroll
        for (int q = 0; q < 4; ++q) acc[f][q] = 0.0f;

    const int rA = (w * 16 + gp) * 260, rB = (w * 16 + gp + 8) * 260;

    for (int q = 0; q < XP_TB * 4; ++q) {
        if (q < XP_TB * 4 - 1) {
            int qn = q + 1;
            int tl = qn >> 2, c = qn & 3;
            const unsigned* Bsrc = g_xt32 + (size_t)(t0 + tl) * BSZ * DSZ + c * 64;
            unsigned* dB = sB + (qn & 1) * 8704;
#pragma unroll
            for (int i = 0; i < 8; ++i) {
                int linear = tid + i * 256;
                int row = linear >> 4, slot = (linear & 15) * 4;
                cp16(&dB[row * 68 + slot], &Bsrc[row * 256 + slot]);
            }
            asm volatile("cp.async.commit_group;");
            asm volatile("cp.async.wait_group 1;");
        } else {
            asm volatile("cp.async.wait_group 0;");
        }
        __syncthreads();
        const unsigned* B = sB + (q & 1) * 8704;
        const int kofs = (q & 3) * 64;
#pragma unroll
        for (int ksl = 0; ksl < 8; ++ksl) {
            int k0 = ksl * 8 + tg;
            unsigned a0 = sA[rA + kofs + k0];
            unsigned a1 = sA[rB + kofs + k0];
            unsigned a2 = sA[rA + kofs + k0 + 4];
            unsigned a3 = sA[rB + kofs + k0 + 4];
#pragma unroll
            for (int f = 0; f < 16; ++f) {
                unsigned b0 = B[(f * 8 + gp) * 68 + k0];
                unsigned b1 = B[(f * 8 + gp) * 68 + k0 + 4];
                MMA_TF32(acc[f][0], acc[f][1], acc[f][2], acc[f][3],
                         a0, a1, a2, a3, b0, b1);
            }
        }
        __syncthreads();

        if ((q & 3) == 3) {
            int t = t0 + (q >> 2);
            const size_t rbase = ((size_t)t * 2048 + M0 + w * 16 + gp) * 128;
#pragma unroll
            for (int f = 0; f < 16; ++f) {
                *(float2*)&g_P[rbase + f * 8 + tg * 2] =
                    make_float2(acc[f][0], acc[f][1]);
                *(float2*)&g_P[rbase + (size_t)8 * 128 + f * 8 + tg * 2] =
                    make_float2(acc[f][2], acc[f][3]);
                acc[f][0] = acc[f][1] = acc[f][2] = acc[f][3] = 0.0f;
            }
        }
    }
}

// ---------------------------------------------------------------------------
// Phase 2: persistent tf32-mma scan with TMA-bulk h staging (R11/R14 proven
// structure; only the activation implementations changed — MUFU-free).
// 128 CTAs = 32 row-groups (mg) x 4 batch-groups (ng).
// SMEM: A 131072 B | h 32x516x4 = 66048 B | E 64x34x4 = 8704 B -> 205824 B
// ---------------------------------------------------------------------------
__global__ __launch_bounds__(256, 1) void k_rnn4(
    const float* __restrict__ Wgh, const float* __restrict__ Wih,
    const float* __restrict__ Wfh, const float* __restrict__ Woh,
    const float* __restrict__ bgp, const float* __restrict__ bip,
    const float* __restrict__ bfp, const float* __restrict__ bop)
{
    extern __shared__ float sm[];
    unsigned* sAu = (unsigned*)sm;          // 32768 u
    float* sh_h = sm + 32768;               // 32 x 516
    float* sh_E = sm + 32768 + 32 * HPAD;   // 64 x 34
    __shared__ __align__(8) unsigned long long mbar_store;
    const unsigned mbar = (unsigned)__cvta_generic_to_shared(&mbar_store);

    const int ct = blockIdx.x;
    const int mg = ct >> 2, ng = ct & 3;
    const int j0 = mg * 16;
    const int nbase = ng * 32;
    const int tid = threadIdx.x;
    const int w = tid >> 5, lane = tid & 31;
    const int mt = w & 3, nh = w >> 2;
    const int gp = lane >> 2, tg = lane & 3;

    // build pre-swizzled tf32 A fragments (once)
    {
        const float* Wt[4] = {Wgh, Wih, Wfh, Woh};
        for (int idx = tid; idx < 32768; idx += 256) {
            int mtb = idx >> 13;
            int rem = idx & 8191;
            int ks = rem >> 7;
            int ln = (rem >> 2) & 31;
            int q = rem & 3;
            int gpp = ln >> 2, tgg = ln & 3;
            int rowl = mtb * 16 + gpp + ((q & 1) << 3);
            int k = ks * 8 + tgg + ((q >> 1) << 2);
            int gate = rowl & 3;
            int j = j0 + (rowl >> 2);
            sAu[idx] = cvt_tf32(Wt[gate][(size_t)k * HSZ + j]);
        }
    }

    const int mA = mt * 16 + gp, mB = mA + 8;
    const int gateA = mA & 3, gateB = mB & 3;
    const int jA = j0 + (mA >> 2), jB = j0 + (mB >> 2);
    const size_t rowA = (size_t)gateA * HSZ + jA;
    const size_t rowB = (size_t)gateB * HSZ + jB;
    const int cb = nbase + nh * 16 + tg * 2;

    const float* Bt0[4] = {bgp, bip, bfp, bop};
    const float biasA = Bt0[gateA][jA];
    const float biasB = Bt0[gateB][jB];

    const int e_jj = tid >> 4;
    const int e_b = (tid & 15) * 2;
    const int e_jglob = j0 + e_jj;
    const int e_bglob = nbase + e_b;

    // init: zero h[0] (incl. padding), reset own flag, init mbarrier
    for (int i = tid; i < HPAD; i += 256) g_h2[0][(size_t)ct * HPAD + i] = 0.0f;
    if (tid == 0) {
        *(volatile unsigned*)&g_flags[ct * 8] = 0u;
        mbar_init(mbar, 1u);
    }
    grid_barrier(gridDim.x);

    float cst0 = 0.0f, cst1 = 0.0f;

    float2 pf0a, pf0b, pf1a, pf1b;
    {
        const float* P0 = g_P;
        pf0a = *(const float2*)&P0[rowA * 128 + cb];
        pf0b = *(const float2*)&P0[rowB * 128 + cb];
        pf1a = *(const float2*)&P0[rowA * 128 + cb + 8];
        pf1b = *(const float2*)&P0[rowB * 128 + cb + 8];
    }

    const unsigned* Abase = sAu + (mt * 64) * 128 + lane * 4;
    const int nAo = (nh * 16 + gp) * HPAD;
    const int nBo = (nh * 16 + 8 + gp) * HPAD;
    const unsigned sh_h_u32 = (unsigned)__cvta_generic_to_shared(sh_h);

    for (int t = 0; t < TSTEPS; ++t) {
        const float* hb = g_h2[t & 1];
        float* hn = g_h2[(t + 1) & 1];

        // warp 0 FIRST: wait for all 32 group writers, then issue bulk
        if (w == 0) {
            const unsigned* f = &g_flags[(lane * 4 + ng) * 8];
            unsigned v;
            while (true) {
                asm volatile("ld.acquire.gpu.u32 %0, [%1];" : "=r"(v) : "l"(f) : "memory");
                if (v >= (unsigned)t) break;
                __nanosleep(20);
            }
            __syncwarp();
            if (lane == 0) {
                mbar_expect_tx(mbar, 32u * HPAD * 4u);
                bulk_g2s(sh_h_u32, hb + (size_t)nbase * HPAD, 32u * HPAD * 4u, mbar);
            }
        }

        float ae0 = pf0a.x + biasA, ae1 = pf0a.y + biasA;
        float ae2 = pf0b.x + biasB, ae3 = pf0b.y + biasB;
        float ae4 = pf1a.x + biasA, ae5 = pf1a.y + biasA;
        float ae6 = pf1b.x + biasB, ae7 = pf1b.y + biasB;
        float ao0 = 0, ao1 = 0, ao2 = 0, ao3 = 0;
        float ao4 = 0, ao5 = 0, ao6 = 0, ao7 = 0;

        if (t + 1 < TSTEPS) {
            const float* Pn = g_P + (size_t)(t + 1) * 2048 * 128;
            pf0a = *(const float2*)&Pn[rowA * 128 + cb];
            pf0b = *(const float2*)&Pn[rowB * 128 + cb];
            pf1a = *(const float2*)&Pn[rowA * 128 + cb + 8];
            pf1b = *(const float2*)&Pn[rowB * 128 + cb + 8];
        }

        // all threads wait for the TMA deposit
        mbar_wait(mbar, (unsigned)(t & 1));

        const unsigned* hu = (const unsigned*)sh_h;
#pragma unroll 8
        for (int k2 = 0; k2 < 32; ++k2) {
            uint4 a0 = *(const uint4*)&Abase[(k2 * 2) * 128];
            uint4 a1 = *(const uint4*)&Abase[(k2 * 2 + 1) * 128];
            int k0 = k2 * 16 + tg;
            int k1 = k0 + 8;
            unsigned b00 = hu[nAo + k0], b01 = hu[nAo + k0 + 4];
            MMA_TF32(ae0, ae1, ae2, ae3, a0.x, a0.y, a0.z, a0.w, b00, b01);
            unsigned b10 = hu[nBo + k0], b11 = hu[nBo + k0 + 4];
            MMA_TF32(ae4, ae5, ae6, ae7, a0.x, a0.y, a0.z, a0.w, b10, b11);
            unsigned d00 = hu[nAo + k1], d01 = hu[nAo + k1 + 4];
            MMA_TF32(ao0, ao1, ao2, ao3, a1.x, a1.y, a1.z, a1.w, d00, d01);
            unsigned d10 = hu[nBo + k1], d11 = hu[nBo + k1 + 4];
            MMA_TF32(ao4, ao5, ao6, ao7, a1.x, a1.y, a1.z, a1.w, d10, d11);
        }

        // exchange preacts
        {
            int col0 = nh * 16 + tg * 2;
            *(float2*)&sh_E[mA * 34 + col0]     = make_float2(ae0 + ao0, ae1 + ao1);
            *(float2*)&sh_E[mB * 34 + col0]     = make_float2(ae2 + ao2, ae3 + ao3);
            *(float2*)&sh_E[mA * 34 + col0 + 8] = make_float2(ae4 + ao4, ae5 + ao5);
            *(float2*)&sh_E[mB * 34 + col0 + 8] = make_float2(ae6 + ao6, ae7 + ao7);
        }
        __syncthreads();

        // epilogue: gates for (e_jj, e_b) and (e_jj, e_b+1) — MUFU-free
        {
            const float* E0 = &sh_E[(e_jj * 4 + 0) * 34 + e_b];
            const float* E1 = &sh_E[(e_jj * 4 + 1) * 34 + e_b];
            const float* E2 = &sh_E[(e_jj * 4 + 2) * 34 + e_b];
            const float* E3 = &sh_E[(e_jj * 4 + 3) * 34 + e_b];
            float gv0 = fast_tanh(E0[0]),    gv1 = fast_tanh(E0[1]);
            float iv0 = fast_sigmoid(E1[0]), iv1 = fast_sigmoid(E1[1]);
            float fv0 = fast_sigmoid(E2[0]), fv1 = fast_sigmoid(E2[1]);
            float ov0 = fast_sigmoid(E3[0]), ov1 = fast_sigmoid(E3[1]);
            cst0 = gv0 * iv0 + cst0 * fv0;
            cst1 = gv1 * iv1 + cst1 * fv1;
            ((unsigned*)hn)[(size_t)e_bglob * HPAD + e_jglob] =
                cvt_tf32(fast_tanh(cst0) * ov0);
            ((unsigned*)hn)[(size_t)(e_bglob + 1) * HPAD + e_jglob] =
                cvt_tf32(fast_tanh(cst1) * ov1);
        }
        __syncthreads();
        if (tid == 0) publish_flag(ct, (unsigned)(t + 1));
    }
}

// ---------------------------------------------------------------------------
// Phase 3: out[b][c] = h_final[b] . Wph[:,c] + bp[c].
// ---------------------------------------------------------------------------
__global__ __launch_bounds__(256) void k_out(
    const float* __restrict__ Wp, const float* __restrict__ bp,
    float* __restrict__ out)
{
    __shared__ float sh[HSZ];
    int b = blockIdx.x;
    const float* h = g_h2[0] + (size_t)b * HPAD;   // t=1023 writes buffer (1024&1)=0
    for (int i = threadIdx.x; i < HSZ; i += 256) sh[i] = h[i];
    __syncthreads();
    for (int c = threadIdx.x; c < CSZ; c += 256) {
        float acc = 0.0f;
#pragma unroll 8
        for (int k = 0; k < HSZ; ++k)
            acc += sh[k] * Wp[(size_t)k * CSZ + c];
        out[b * CSZ + c] = acc + bp[c];
    }
}

// ---------------------------------------------------------------------------

extern "C" void kernel_launch(void* const* d_in, const int* in_sizes, int n_in,
                              void* d_out, int out_size) {
    const float* x   = (const float*)d_in[0];
    const float* Wgx = (const float*)d_in[1];
    const float* Wgh = (const float*)d_in[2];
    const float* bg  = (const float*)d_in[3];
    const float* Wix = (const float*)d_in[4];
    const float* Wih = (const float*)d_in[5];
    const float* bi  = (const float*)d_in[6];
    const float* Wfx = (const float*)d_in[7];
    const float* Wfh = (const float*)d_in[8];
    const float* bf  = (const float*)d_in[9];
    const float* Wox = (const float*)d_in[10];
    const float* Woh = (const float*)d_in[11];
    const float* bo  = (const float*)d_in[12];
    const float* Wph = (const float*)d_in[13];
    const float* bp  = (const float*)d_in[14];
    float* out = (float*)d_out;

    (void)in_sizes; (void)n_in; (void)out_size;

    const int smem_xp  = 202752;                                 // A 133120 + B 69632
    const int smem_rnn = (32768 + 32 * HPAD + 64 * 34) * 4;      // 205824 B
    cudaFuncSetAttribute(k_xproj3, cudaFuncAttributeMaxDynamicSharedMemorySize, smem_xp);
    cudaFuncSetAttribute(k_rnn4,   cudaFuncAttributeMaxDynamicSharedMemorySize, smem_rnn);

    k_prep_w<<<2048, 256>>>(Wgx, Wix, Wfx, Wox);
    k_prep_x<<<dim3(TSTEPS, BSZ), 64>>>(x);
    k_xproj3<<<dim3(16, TSTEPS / XP_TB), 256, smem_xp>>>();
    k_rnn4<<<128, 256, smem_rnn>>>(Wgh, Wih, Wfh, Woh, bg, bi, bf, bo);
    k_out<<<BSZ, 256>>>(Wph, bp, out);
}